// round 3
// baseline (speedup 1.0000x reference)
#include <cuda_runtime.h>
#include <cuda_bf16.h>
#include <cstdint>
#include <cstddef>

// ---------------------------------------------------------------------------
// Problem constants (fixed shapes: B=2, S=2048, E=2048, H=16, D=128)
// ---------------------------------------------------------------------------
#define BSZ   2
#define SEQ   2048
#define EMB   2048
#define NHEAD 16
#define HDIM  128
#define MROWS (BSZ * SEQ)      /* 4096 */
#define NQKV  (3 * EMB)        /* 6144 */

#define QK_SCALE 0.08838834764831845f  /* 128^-0.5 */

// ---------------------------------------------------------------------------
// Scratch (no cudaMalloc allowed -> __device__ globals)
// ---------------------------------------------------------------------------
__device__ float g_qkv[(size_t)MROWS * NQKV];                 // ~100 MB
__device__ float g_q[(size_t)BSZ * NHEAD * SEQ * HDIM];       // 33.6 MB
__device__ float g_k[(size_t)BSZ * NHEAD * SEQ * HDIM];
__device__ float g_v[(size_t)BSZ * NHEAD * SEQ * HDIM];
__device__ float g_att[(size_t)MROWS * EMB];                  // 33.6 MB

// ---------------------------------------------------------------------------
// SGEMM: C[M,N] = A[M,K] @ B[K,N], fp32, all dims multiples of tile sizes.
// 128x128x16 tiles, 256 threads, 8x8 microtile, cp.async double buffer.
// ---------------------------------------------------------------------------
__device__ __forceinline__ uint32_t smem_addr_u32(const void* p) {
    return (uint32_t)__cvta_generic_to_shared(p);
}

__global__ __launch_bounds__(256, 2)
void sgemm_kernel(const float* __restrict__ A, const float* __restrict__ B,
                  float* __restrict__ C, int M, int N, int K)
{
    __shared__ float As[2][128][16];   // [m][k]
    __shared__ float Bs[2][16][128];   // [k][n]

    const int tid = threadIdx.x;
    const int tx = tid & 15;
    const int ty = tid >> 4;
    const int m0 = blockIdx.y << 7;
    const int n0 = blockIdx.x << 7;

    const int a_c  = (tid & 3) << 2;   // k offset within tile (0,4,8,12)
    const int a_r  = tid >> 2;         // row 0..63 (+64 on 2nd chunk)
    const int b_c4 = (tid & 31) << 2;  // col offset 0..124
    const int b_kr = tid >> 5;         // k row 0..7 (+8 on 2nd chunk)

    float acc[8][8];
#pragma unroll
    for (int i = 0; i < 8; i++)
#pragma unroll
        for (int j = 0; j < 8; j++) acc[i][j] = 0.f;

    const int nk = K >> 4;

    auto issue = [&](int t, int buf) {
        const int k0 = t << 4;
#pragma unroll
        for (int it = 0; it < 2; ++it) {
            int row = a_r + it * 64;
            const float* ga = A + (size_t)(m0 + row) * K + k0 + a_c;
            uint32_t sa = smem_addr_u32(&As[buf][row][a_c]);
            asm volatile("cp.async.ca.shared.global [%0], [%1], 16;\n"
                         :: "r"(sa), "l"(ga));
            int kr = b_kr + it * 8;
            const float* gb = B + (size_t)(k0 + kr) * N + n0 + b_c4;
            uint32_t sb = smem_addr_u32(&Bs[buf][kr][b_c4]);
            asm volatile("cp.async.ca.shared.global [%0], [%1], 16;\n"
                         :: "r"(sb), "l"(gb));
        }
        asm volatile("cp.async.commit_group;\n");
    };

    issue(0, 0);
    for (int t = 0; t < nk; ++t) {
        if (t + 1 < nk) {
            issue(t + 1, (t + 1) & 1);
            asm volatile("cp.async.wait_group 1;\n");
        } else {
            asm volatile("cp.async.wait_group 0;\n");
        }
        __syncthreads();
        const int buf = t & 1;
#pragma unroll
        for (int kk = 0; kk < 16; ++kk) {
            float a[8], b[8];
#pragma unroll
            for (int i = 0; i < 8; i++) a[i] = As[buf][ty * 8 + i][kk];
            float4 bv0 = *(const float4*)&Bs[buf][kk][tx * 8];
            float4 bv1 = *(const float4*)&Bs[buf][kk][tx * 8 + 4];
            b[0] = bv0.x; b[1] = bv0.y; b[2] = bv0.z; b[3] = bv0.w;
            b[4] = bv1.x; b[5] = bv1.y; b[6] = bv1.z; b[7] = bv1.w;
#pragma unroll
            for (int i = 0; i < 8; i++)
#pragma unroll
                for (int j = 0; j < 8; j++)
                    acc[i][j] = fmaf(a[i], b[j], acc[i][j]);
        }
        __syncthreads();
    }

    // epilogue (dims divide evenly: no guards)
#pragma unroll
    for (int i = 0; i < 8; i++) {
        float4 o0 = make_float4(acc[i][0], acc[i][1], acc[i][2], acc[i][3]);
        float4 o1 = make_float4(acc[i][4], acc[i][5], acc[i][6], acc[i][7]);
        float* cp = C + (size_t)(m0 + ty * 8 + i) * N + n0 + tx * 8;
        *(float4*)cp = o0;
        *(float4*)(cp + 4) = o1;
    }
}

// ---------------------------------------------------------------------------
// RoPE + reorder: qkv [B*S, 3E] -> Q/K/V [B, H, S, D], q pre-scaled by D^-0.5
// One thread per (b, h, s, pair i).  t bits: i:6, h:4, s:11, b:1 -> 2^22 thrds
// ---------------------------------------------------------------------------
__global__ void rope_split_kernel(const float* __restrict__ qkv,
                                  const float* __restrict__ freqs)
{
    int t = blockIdx.x * blockDim.x + threadIdx.x;
    int i = t & 63;
    int h = (t >> 6) & 15;
    int s = (t >> 10) & 2047;
    int b = t >> 21;

    size_t row = (size_t)(b * SEQ + s) * NQKV + h * HDIM;
    float2 q  = *(const float2*)&qkv[row + 2 * i];
    float2 k  = *(const float2*)&qkv[row + EMB + 2 * i];
    float2 v  = *(const float2*)&qkv[row + 2 * EMB + 2 * i];
    float2 cs = *(const float2*)&freqs[(size_t)s * HDIM + 2 * i];  // (cos, sin)

    float qre = (q.x * cs.x - q.y * cs.y) * QK_SCALE;
    float qim = (q.y * cs.x + q.x * cs.y) * QK_SCALE;
    float kre = k.x * cs.x - k.y * cs.y;
    float kim = k.y * cs.x + k.x * cs.y;

    size_t o = ((size_t)(b * NHEAD + h) * SEQ + s) * HDIM + 2 * i;
    *(float2*)&g_q[o] = make_float2(qre, qim);
    *(float2*)&g_k[o] = make_float2(kre, kim);
    *(float2*)&g_v[o] = v;
}

// ---------------------------------------------------------------------------
// Flash attention (causal), fp32.  BM=BN=64, D=128.
// 256 threads = 16x16 grid. S microtile 4x4 (cols tx+16j), O microtile 4x8.
// Smem rows padded to 132 floats (16B-aligned, low conflict).
// ---------------------------------------------------------------------------
#define FA_PAD  132
#define FA_PPAD 68
#define FA_SMEM_FLOATS (3 * 64 * FA_PAD + 64 * FA_PPAD)
#define FA_SMEM_BYTES  (FA_SMEM_FLOATS * 4)

extern __shared__ float fa_smem[];

__global__ __launch_bounds__(256, 1)
void flash_kernel()
{
    float* Qs = fa_smem;                 // [64][132]
    float* Ks = Qs + 64 * FA_PAD;        // [64][132]
    float* Vs = Ks + 64 * FA_PAD;        // [64][132]
    float* Ps = Vs + 64 * FA_PAD;        // [64][68]

    const int tid = threadIdx.x;
    const int tx = tid & 15;
    const int ty = tid >> 4;
    const int qb = blockIdx.x;           // 0..31
    const int h  = blockIdx.y;
    const int b  = blockIdx.z;

    const size_t base = (size_t)(b * NHEAD + h) * SEQ * HDIM;
    const float* Qg = g_q + base + (size_t)qb * 64 * HDIM;
    const float* Kg = g_k + base;
    const float* Vg = g_v + base;

    // load Q tile once
#pragma unroll
    for (int it = 0; it < 8; ++it) {
        int u = tid + it * 256;          // 0..2047
        int n  = u >> 5;
        int d4 = (u & 31) << 2;
        *(float4*)&Qs[n * FA_PAD + d4] = *(const float4*)&Qg[(size_t)n * HDIM + d4];
    }

    float m_i[4], l_i[4], accO[4][8];
#pragma unroll
    for (int i = 0; i < 4; i++) {
        m_i[i] = -1e30f; l_i[i] = 0.f;
#pragma unroll
        for (int c = 0; c < 8; c++) accO[i][c] = 0.f;
    }

    int qrow[4], prow[4], krow[4];
#pragma unroll
    for (int i = 0; i < 4; i++) {
        qrow[i] = (ty * 4 + i) * FA_PAD;
        prow[i] = (ty * 4 + i) * FA_PPAD;
        krow[i] = (tx + 16 * i) * FA_PAD;
    }

    const int nkb = qb + 1;
    for (int kb = 0; kb < nkb; ++kb) {
        __syncthreads();   // previous P/V reads done (and Q load visible)
        // load K, V tiles
#pragma unroll
        for (int it = 0; it < 8; ++it) {
            int u = tid + it * 256;
            int n  = u >> 5;
            int d4 = (u & 31) << 2;
            size_t gofs = (size_t)(kb * 64 + n) * HDIM + d4;
            *(float4*)&Ks[n * FA_PAD + d4] = *(const float4*)&Kg[gofs];
            *(float4*)&Vs[n * FA_PAD + d4] = *(const float4*)&Vg[gofs];
        }
        __syncthreads();

        // ---- S = Q . K^T  (Q pre-scaled) ----
        float accS[4][4];
#pragma unroll
        for (int i = 0; i < 4; i++)
#pragma unroll
            for (int j = 0; j < 4; j++) accS[i][j] = 0.f;

#pragma unroll 4
        for (int kk = 0; kk < 128; ++kk) {
            float a0 = Qs[qrow[0] + kk];
            float a1 = Qs[qrow[1] + kk];
            float a2 = Qs[qrow[2] + kk];
            float a3 = Qs[qrow[3] + kk];
            float b0 = Ks[krow[0] + kk];
            float b1 = Ks[krow[1] + kk];
            float b2 = Ks[krow[2] + kk];
            float b3 = Ks[krow[3] + kk];
            accS[0][0] = fmaf(a0, b0, accS[0][0]);
            accS[0][1] = fmaf(a0, b1, accS[0][1]);
            accS[0][2] = fmaf(a0, b2, accS[0][2]);
            accS[0][3] = fmaf(a0, b3, accS[0][3]);
            accS[1][0] = fmaf(a1, b0, accS[1][0]);
            accS[1][1] = fmaf(a1, b1, accS[1][1]);
            accS[1][2] = fmaf(a1, b2, accS[1][2]);
            accS[1][3] = fmaf(a1, b3, accS[1][3]);
            accS[2][0] = fmaf(a2, b0, accS[2][0]);
            accS[2][1] = fmaf(a2, b1, accS[2][1]);
            accS[2][2] = fmaf(a2, b2, accS[2][2]);
            accS[2][3] = fmaf(a2, b3, accS[2][3]);
            accS[3][0] = fmaf(a3, b0, accS[3][0]);
            accS[3][1] = fmaf(a3, b1, accS[3][1]);
            accS[3][2] = fmaf(a3, b2, accS[3][2]);
            accS[3][3] = fmaf(a3, b3, accS[3][3]);
        }

        // ---- causal mask (diagonal block only) ----
        if (kb == qb) {
#pragma unroll
            for (int i = 0; i < 4; i++) {
                int qi = ty * 4 + i;
#pragma unroll
                for (int j = 0; j < 4; j++) {
                    int ki = tx + 16 * j;
                    if (ki > qi) accS[i][j] = -1e30f;
                }
            }
        }

        // ---- online softmax update ----
#pragma unroll
        for (int i = 0; i < 4; i++) {
            float mx = fmaxf(fmaxf(accS[i][0], accS[i][1]),
                             fmaxf(accS[i][2], accS[i][3]));
            mx = fmaxf(mx, __shfl_xor_sync(0xffffffffu, mx, 1));
            mx = fmaxf(mx, __shfl_xor_sync(0xffffffffu, mx, 2));
            mx = fmaxf(mx, __shfl_xor_sync(0xffffffffu, mx, 4));
            mx = fmaxf(mx, __shfl_xor_sync(0xffffffffu, mx, 8));
            float mnew = fmaxf(m_i[i], mx);
            float scale = __expf(m_i[i] - mnew);
            float rs = 0.f;
#pragma unroll
            for (int j = 0; j < 4; j++) {
                float p = __expf(accS[i][j] - mnew);
                Ps[prow[i] + tx + 16 * j] = p;
                rs += p;
            }
            rs += __shfl_xor_sync(0xffffffffu, rs, 1);
            rs += __shfl_xor_sync(0xffffffffu, rs, 2);
            rs += __shfl_xor_sync(0xffffffffu, rs, 4);
            rs += __shfl_xor_sync(0xffffffffu, rs, 8);
            l_i[i] = l_i[i] * scale + rs;
            m_i[i] = mnew;
#pragma unroll
            for (int c = 0; c < 8; c++) accO[i][c] *= scale;
        }
        __syncthreads();   // Ps visible to all

        // ---- O += P . V ----
#pragma unroll 2
        for (int n = 0; n < 64; ++n) {
            float4 v0 = *(const float4*)&Vs[n * FA_PAD + tx * 8];
            float4 v1 = *(const float4*)&Vs[n * FA_PAD + tx * 8 + 4];
#pragma unroll
            for (int i = 0; i < 4; i++) {
                float p = Ps[prow[i] + n];
                accO[i][0] = fmaf(p, v0.x, accO[i][0]);
                accO[i][1] = fmaf(p, v0.y, accO[i][1]);
                accO[i][2] = fmaf(p, v0.z, accO[i][2]);
                accO[i][3] = fmaf(p, v0.w, accO[i][3]);
                accO[i][4] = fmaf(p, v1.x, accO[i][4]);
                accO[i][5] = fmaf(p, v1.y, accO[i][5]);
                accO[i][6] = fmaf(p, v1.z, accO[i][6]);
                accO[i][7] = fmaf(p, v1.w, accO[i][7]);
            }
        }
    }

    // ---- epilogue: normalize + write [B, S, H*D] ----
#pragma unroll
    for (int i = 0; i < 4; i++) {
        float inv = 1.f / l_i[i];
        int s = qb * 64 + ty * 4 + i;
        float* op = g_att + (size_t)(b * SEQ + s) * EMB + h * HDIM + tx * 8;
        float4 o0 = make_float4(accO[i][0] * inv, accO[i][1] * inv,
                                accO[i][2] * inv, accO[i][3] * inv);
        float4 o1 = make_float4(accO[i][4] * inv, accO[i][5] * inv,
                                accO[i][6] * inv, accO[i][7] * inv);
        *(float4*)op = o0;
        *(float4*)(op + 4) = o1;
    }
}

// ---------------------------------------------------------------------------
// Launcher
// ---------------------------------------------------------------------------
extern "C" void kernel_launch(void* const* d_in, const int* in_sizes, int n_in,
                              void* d_out, int out_size)
{
    const float* x     = (const float*)d_in[0];  // [B, S, E]
    const float* Wqkv  = (const float*)d_in[1];  // [E, 3E]
    const float* Wo    = (const float*)d_in[2];  // [E, E]
    const float* freqs = (const float*)d_in[3];  // [S, 1, D/2, 2]
    float* out = (float*)d_out;                  // [B, S, E]

    float *p_qkv = nullptr, *p_att = nullptr;
    cudaGetSymbolAddress((void**)&p_qkv, g_qkv);
    cudaGetSymbolAddress((void**)&p_att, g_att);

    cudaFuncSetAttribute(flash_kernel,
                         cudaFuncAttributeMaxDynamicSharedMemorySize,
                         FA_SMEM_BYTES);

    // 1) qkv = x @ Wqkv
    {
        dim3 grid(NQKV / 128, MROWS / 128);  // 48 x 32
        sgemm_kernel<<<grid, 256>>>(x, Wqkv, p_qkv, MROWS, NQKV, EMB);
    }
    // 2) RoPE + split/transpose to [B,H,S,D]
    {
        int total = BSZ * SEQ * NHEAD * (HDIM / 2);  // 2^22
        rope_split_kernel<<<total / 256, 256>>>(p_qkv, freqs);
    }
    // 3) causal flash attention
    {
        dim3 grid(SEQ / 64, NHEAD, BSZ);     // 32 x 16 x 2
        flash_kernel<<<grid, 256, FA_SMEM_BYTES>>>();
    }
    // 4) out = att @ Wo
    {
        dim3 grid(EMB / 128, MROWS / 128);   // 16 x 32
        sgemm_kernel<<<grid, 256>>>(p_att, Wo, out, MROWS, EMB, EMB);
    }
}

// round 4
// speedup vs baseline: 1.8129x; 1.8129x over previous
#include <cuda_runtime.h>
#include <cuda_bf16.h>
#include <cstdint>
#include <cstddef>

// ---------------------------------------------------------------------------
// Problem constants (fixed shapes: B=2, S=2048, E=2048, H=16, D=128)
// ---------------------------------------------------------------------------
#define BSZ   2
#define SEQ   2048
#define EMB   2048
#define NHEAD 16
#define HDIM  128
#define MROWS (BSZ * SEQ)      /* 4096 */
#define NQKV  (3 * EMB)        /* 6144 */

#define QK_SCALE 0.08838834764831845f  /* 128^-0.5 */

// ---------------------------------------------------------------------------
// Scratch (no cudaMalloc allowed -> __device__ globals)
// ---------------------------------------------------------------------------
__device__ float g_qkv[(size_t)MROWS * NQKV];                 // ~100 MB
__device__ float g_q[(size_t)BSZ * NHEAD * SEQ * HDIM];       // 33.6 MB
__device__ float g_k[(size_t)BSZ * NHEAD * SEQ * HDIM];
__device__ float g_v[(size_t)BSZ * NHEAD * SEQ * HDIM];
__device__ float g_att[(size_t)MROWS * EMB];                  // 33.6 MB

// ---------------------------------------------------------------------------
// TF32 tensor-core GEMM: C[M,N] = A[M,K] @ B[K,N].
// CTA tile 128x128x32, 256 threads = 8 warps (2x4), warp tile 64x32,
// mma.sync.m16n8k8.tf32. Inputs rounded with cvt.rna.tf32 at the smem store.
// ---------------------------------------------------------------------------
#define GBM 128
#define GBN 128
#define GBK 32
#define APITCH 36    /* floats per As row  ([m][k])  -> a-frag banks 4g+t, distinct */
#define BPITCH 136   /* floats per Bs row  ([k][n])  -> b-frag banks 8t+g, distinct */

__device__ __forceinline__ uint32_t f2tf32(float f) {
    uint32_t r;
    asm("cvt.rna.tf32.f32 %0, %1;" : "=r"(r) : "f"(f));
    return r;
}

__device__ __forceinline__ void mma_tf32(float& d0, float& d1, float& d2, float& d3,
                                         uint32_t a0, uint32_t a1, uint32_t a2, uint32_t a3,
                                         uint32_t b0, uint32_t b1)
{
    asm volatile(
        "mma.sync.aligned.m16n8k8.row.col.f32.tf32.tf32.f32 "
        "{%0,%1,%2,%3}, {%4,%5,%6,%7}, {%8,%9}, {%0,%1,%2,%3};"
        : "+f"(d0), "+f"(d1), "+f"(d2), "+f"(d3)
        : "r"(a0), "r"(a1), "r"(a2), "r"(a3), "r"(b0), "r"(b1));
}

__global__ __launch_bounds__(256)
void tf32_gemm_kernel(const float* __restrict__ A, const float* __restrict__ B,
                      float* __restrict__ C, int M, int N, int K)
{
    __shared__ uint32_t As[GBM * APITCH];   // [m][k], pitch 36
    __shared__ uint32_t Bs[GBK * BPITCH];   // [k][n], pitch 136

    const int tid  = threadIdx.x;
    const int lane = tid & 31;
    const int w    = tid >> 5;         // 0..7
    const int wm   = (w >> 2) * 64;    // warp row offset (0 or 64)
    const int wn   = (w & 3) * 32;     // warp col offset (0,32,64,96)
    const int g    = lane >> 2;        // 0..7
    const int t4   = lane & 3;         // 0..3

    const int m0 = blockIdx.y * GBM;
    const int n0 = blockIdx.x * GBN;

    // global-load assignments (coalesced LDG.128)
    const int a_row = tid >> 3;            // 0..31 (+32*it)
    const int a_c4  = (tid & 7) << 2;      // 0..28
    const int b_row = tid >> 5;            // 0..7  (+8*it)
    const int b_c4  = (tid & 31) << 2;     // 0..124

    const float* aP = A + (size_t)(m0 + a_row) * K + a_c4;
    const float* bP = B + (size_t)b_row * N + n0 + b_c4;

    float4 ra[4], rb[4];
    float d[4][4][4];
#pragma unroll
    for (int i = 0; i < 4; i++)
#pragma unroll
        for (int j = 0; j < 4; j++)
#pragma unroll
            for (int c = 0; c < 4; c++) d[i][j][c] = 0.f;

    const int nk = K / GBK;

    // prologue: load tile 0
#pragma unroll
    for (int it = 0; it < 4; ++it) {
        ra[it] = *(const float4*)(aP + (size_t)(it * 32) * K);
        rb[it] = *(const float4*)(bP + (size_t)(it * 8) * N);
    }

    for (int tkt = 0; tkt < nk; ++tkt) {
        __syncthreads();   // all warps done reading smem from previous tile
        // cvt + store current tile to smem
#pragma unroll
        for (int it = 0; it < 4; ++it) {
            uint4 va = make_uint4(f2tf32(ra[it].x), f2tf32(ra[it].y),
                                  f2tf32(ra[it].z), f2tf32(ra[it].w));
            *(uint4*)&As[(a_row + it * 32) * APITCH + a_c4] = va;
            uint4 vb = make_uint4(f2tf32(rb[it].x), f2tf32(rb[it].y),
                                  f2tf32(rb[it].z), f2tf32(rb[it].w));
            *(uint4*)&Bs[(b_row + it * 8) * BPITCH + b_c4] = vb;
        }
        __syncthreads();

        // prefetch next tile into registers
        if (tkt + 1 < nk) {
            const float* aN = aP + (size_t)(tkt + 1) * GBK;
            const float* bN = bP + (size_t)(tkt + 1) * GBK * N;
#pragma unroll
            for (int it = 0; it < 4; ++it) {
                ra[it] = *(const float4*)(aN + (size_t)(it * 32) * K);
                rb[it] = *(const float4*)(bN + (size_t)(it * 8) * N);
            }
        }

        // compute: 4 k-steps of 8
#pragma unroll
        for (int s = 0; s < 4; ++s) {
            const int kc = s * 8;
            uint32_t af[4][4], bf[4][2];
#pragma unroll
            for (int mf = 0; mf < 4; ++mf) {
                int r0 = wm + mf * 16 + g;
                af[mf][0] = As[r0 * APITCH + kc + t4];
                af[mf][1] = As[(r0 + 8) * APITCH + kc + t4];
                af[mf][2] = As[r0 * APITCH + kc + t4 + 4];
                af[mf][3] = As[(r0 + 8) * APITCH + kc + t4 + 4];
            }
#pragma unroll
            for (int nf = 0; nf < 4; ++nf) {
                int c0 = wn + nf * 8 + g;
                bf[nf][0] = Bs[(kc + t4) * BPITCH + c0];
                bf[nf][1] = Bs[(kc + t4 + 4) * BPITCH + c0];
            }
#pragma unroll
            for (int mf = 0; mf < 4; ++mf)
#pragma unroll
                for (int nf = 0; nf < 4; ++nf)
                    mma_tf32(d[mf][nf][0], d[mf][nf][1], d[mf][nf][2], d[mf][nf][3],
                             af[mf][0], af[mf][1], af[mf][2], af[mf][3],
                             bf[nf][0], bf[nf][1]);
        }
    }

    // epilogue: c0/c1 -> (row, 2t), (row, 2t+1); c2/c3 -> row+8
#pragma unroll
    for (int mf = 0; mf < 4; ++mf) {
#pragma unroll
        for (int nf = 0; nf < 4; ++nf) {
            int row = m0 + wm + mf * 16 + g;
            int col = n0 + wn + nf * 8 + 2 * t4;
            float* cp0 = C + (size_t)row * N + col;
            float* cp1 = C + (size_t)(row + 8) * N + col;
            *(float2*)cp0 = make_float2(d[mf][nf][0], d[mf][nf][1]);
            *(float2*)cp1 = make_float2(d[mf][nf][2], d[mf][nf][3]);
        }
    }
}

// ---------------------------------------------------------------------------
// RoPE + reorder: qkv [B*S, 3E] -> Q/K/V [B, H, S, D], q pre-scaled by D^-0.5
// ---------------------------------------------------------------------------
__global__ void rope_split_kernel(const float* __restrict__ qkv,
                                  const float* __restrict__ freqs)
{
    int t = blockIdx.x * blockDim.x + threadIdx.x;
    int i = t & 63;
    int h = (t >> 6) & 15;
    int s = (t >> 10) & 2047;
    int b = t >> 21;

    size_t row = (size_t)(b * SEQ + s) * NQKV + h * HDIM;
    float2 q  = *(const float2*)&qkv[row + 2 * i];
    float2 k  = *(const float2*)&qkv[row + EMB + 2 * i];
    float2 v  = *(const float2*)&qkv[row + 2 * EMB + 2 * i];
    float2 cs = *(const float2*)&freqs[(size_t)s * HDIM + 2 * i];  // (cos, sin)

    float qre = (q.x * cs.x - q.y * cs.y) * QK_SCALE;
    float qim = (q.y * cs.x + q.x * cs.y) * QK_SCALE;
    float kre = k.x * cs.x - k.y * cs.y;
    float kim = k.y * cs.x + k.x * cs.y;

    size_t o = ((size_t)(b * NHEAD + h) * SEQ + s) * HDIM + 2 * i;
    *(float2*)&g_q[o] = make_float2(qre, qim);
    *(float2*)&g_k[o] = make_float2(kre, kim);
    *(float2*)&g_v[o] = v;
}

// ---------------------------------------------------------------------------
// Flash attention (causal), fp32.  BM=BN=64, D=128. (unchanged from R2)
// ---------------------------------------------------------------------------
#define FA_PAD  132
#define FA_PPAD 68
#define FA_SMEM_FLOATS (3 * 64 * FA_PAD + 64 * FA_PPAD)
#define FA_SMEM_BYTES  (FA_SMEM_FLOATS * 4)

extern __shared__ float fa_smem[];

__global__ __launch_bounds__(256, 1)
void flash_kernel()
{
    float* Qs = fa_smem;                 // [64][132]
    float* Ks = Qs + 64 * FA_PAD;        // [64][132]
    float* Vs = Ks + 64 * FA_PAD;        // [64][132]
    float* Ps = Vs + 64 * FA_PAD;        // [64][68]

    const int tid = threadIdx.x;
    const int tx = tid & 15;
    const int ty = tid >> 4;
    const int qb = blockIdx.x;           // 0..31
    const int h  = blockIdx.y;
    const int b  = blockIdx.z;

    const size_t base = (size_t)(b * NHEAD + h) * SEQ * HDIM;
    const float* Qg = g_q + base + (size_t)qb * 64 * HDIM;
    const float* Kg = g_k + base;
    const float* Vg = g_v + base;

    // load Q tile once
#pragma unroll
    for (int it = 0; it < 8; ++it) {
        int u = tid + it * 256;          // 0..2047
        int n  = u >> 5;
        int d4 = (u & 31) << 2;
        *(float4*)&Qs[n * FA_PAD + d4] = *(const float4*)&Qg[(size_t)n * HDIM + d4];
    }

    float m_i[4], l_i[4], accO[4][8];
#pragma unroll
    for (int i = 0; i < 4; i++) {
        m_i[i] = -1e30f; l_i[i] = 0.f;
#pragma unroll
        for (int c = 0; c < 8; c++) accO[i][c] = 0.f;
    }

    int qrow[4], prow[4], krow[4];
#pragma unroll
    for (int i = 0; i < 4; i++) {
        qrow[i] = (ty * 4 + i) * FA_PAD;
        prow[i] = (ty * 4 + i) * FA_PPAD;
        krow[i] = (tx + 16 * i) * FA_PAD;
    }

    const int nkb = qb + 1;
    for (int kb = 0; kb < nkb; ++kb) {
        __syncthreads();   // previous P/V reads done (and Q load visible)
        // load K, V tiles
#pragma unroll
        for (int it = 0; it < 8; ++it) {
            int u = tid + it * 256;
            int n  = u >> 5;
            int d4 = (u & 31) << 2;
            size_t gofs = (size_t)(kb * 64 + n) * HDIM + d4;
            *(float4*)&Ks[n * FA_PAD + d4] = *(const float4*)&Kg[gofs];
            *(float4*)&Vs[n * FA_PAD + d4] = *(const float4*)&Vg[gofs];
        }
        __syncthreads();

        // ---- S = Q . K^T  (Q pre-scaled) ----
        float accS[4][4];
#pragma unroll
        for (int i = 0; i < 4; i++)
#pragma unroll
            for (int j = 0; j < 4; j++) accS[i][j] = 0.f;

#pragma unroll 4
        for (int kk = 0; kk < 128; ++kk) {
            float a0 = Qs[qrow[0] + kk];
            float a1 = Qs[qrow[1] + kk];
            float a2 = Qs[qrow[2] + kk];
            float a3 = Qs[qrow[3] + kk];
            float b0 = Ks[krow[0] + kk];
            float b1 = Ks[krow[1] + kk];
            float b2 = Ks[krow[2] + kk];
            float b3 = Ks[krow[3] + kk];
            accS[0][0] = fmaf(a0, b0, accS[0][0]);
            accS[0][1] = fmaf(a0, b1, accS[0][1]);
            accS[0][2] = fmaf(a0, b2, accS[0][2]);
            accS[0][3] = fmaf(a0, b3, accS[0][3]);
            accS[1][0] = fmaf(a1, b0, accS[1][0]);
            accS[1][1] = fmaf(a1, b1, accS[1][1]);
            accS[1][2] = fmaf(a1, b2, accS[1][2]);
            accS[1][3] = fmaf(a1, b3, accS[1][3]);
            accS[2][0] = fmaf(a2, b0, accS[2][0]);
            accS[2][1] = fmaf(a2, b1, accS[2][1]);
            accS[2][2] = fmaf(a2, b2, accS[2][2]);
            accS[2][3] = fmaf(a2, b3, accS[2][3]);
            accS[3][0] = fmaf(a3, b0, accS[3][0]);
            accS[3][1] = fmaf(a3, b1, accS[3][1]);
            accS[3][2] = fmaf(a3, b2, accS[3][2]);
            accS[3][3] = fmaf(a3, b3, accS[3][3]);
        }

        // ---- causal mask (diagonal block only) ----
        if (kb == qb) {
#pragma unroll
            for (int i = 0; i < 4; i++) {
                int qi = ty * 4 + i;
#pragma unroll
                for (int j = 0; j < 4; j++) {
                    int ki = tx + 16 * j;
                    if (ki > qi) accS[i][j] = -1e30f;
                }
            }
        }

        // ---- online softmax update ----
#pragma unroll
        for (int i = 0; i < 4; i++) {
            float mx = fmaxf(fmaxf(accS[i][0], accS[i][1]),
                             fmaxf(accS[i][2], accS[i][3]));
            mx = fmaxf(mx, __shfl_xor_sync(0xffffffffu, mx, 1));
            mx = fmaxf(mx, __shfl_xor_sync(0xffffffffu, mx, 2));
            mx = fmaxf(mx, __shfl_xor_sync(0xffffffffu, mx, 4));
            mx = fmaxf(mx, __shfl_xor_sync(0xffffffffu, mx, 8));
            float mnew = fmaxf(m_i[i], mx);
            float scale = __expf(m_i[i] - mnew);
            float rs = 0.f;
#pragma unroll
            for (int j = 0; j < 4; j++) {
                float p = __expf(accS[i][j] - mnew);
                Ps[prow[i] + tx + 16 * j] = p;
                rs += p;
            }
            rs += __shfl_xor_sync(0xffffffffu, rs, 1);
            rs += __shfl_xor_sync(0xffffffffu, rs, 2);
            rs += __shfl_xor_sync(0xffffffffu, rs, 4);
            rs += __shfl_xor_sync(0xffffffffu, rs, 8);
            l_i[i] = l_i[i] * scale + rs;
            m_i[i] = mnew;
#pragma unroll
            for (int c = 0; c < 8; c++) accO[i][c] *= scale;
        }
        __syncthreads();   // Ps visible to all

        // ---- O += P . V ----
#pragma unroll 2
        for (int n = 0; n < 64; ++n) {
            float4 v0 = *(const float4*)&Vs[n * FA_PAD + tx * 8];
            float4 v1 = *(const float4*)&Vs[n * FA_PAD + tx * 8 + 4];
#pragma unroll
            for (int i = 0; i < 4; i++) {
                float p = Ps[prow[i] + n];
                accO[i][0] = fmaf(p, v0.x, accO[i][0]);
                accO[i][1] = fmaf(p, v0.y, accO[i][1]);
                accO[i][2] = fmaf(p, v0.z, accO[i][2]);
                accO[i][3] = fmaf(p, v0.w, accO[i][3]);
                accO[i][4] = fmaf(p, v1.x, accO[i][4]);
                accO[i][5] = fmaf(p, v1.y, accO[i][5]);
                accO[i][6] = fmaf(p, v1.z, accO[i][6]);
                accO[i][7] = fmaf(p, v1.w, accO[i][7]);
            }
        }
    }

    // ---- epilogue: normalize + write [B, S, H*D] ----
#pragma unroll
    for (int i = 0; i < 4; i++) {
        float inv = 1.f / l_i[i];
        int s = qb * 64 + ty * 4 + i;
        float* op = g_att + (size_t)(b * SEQ + s) * EMB + h * HDIM + tx * 8;
        float4 o0 = make_float4(accO[i][0] * inv, accO[i][1] * inv,
                                accO[i][2] * inv, accO[i][3] * inv);
        float4 o1 = make_float4(accO[i][4] * inv, accO[i][5] * inv,
                                accO[i][6] * inv, accO[i][7] * inv);
        *(float4*)op = o0;
        *(float4*)(op + 4) = o1;
    }
}

// ---------------------------------------------------------------------------
// Launcher
// ---------------------------------------------------------------------------
extern "C" void kernel_launch(void* const* d_in, const int* in_sizes, int n_in,
                              void* d_out, int out_size)
{
    const float* x     = (const float*)d_in[0];  // [B, S, E]
    const float* Wqkv  = (const float*)d_in[1];  // [E, 3E]
    const float* Wo    = (const float*)d_in[2];  // [E, E]
    const float* freqs = (const float*)d_in[3];  // [S, 1, D/2, 2]
    float* out = (float*)d_out;                  // [B, S, E]

    float *p_qkv = nullptr, *p_att = nullptr;
    cudaGetSymbolAddress((void**)&p_qkv, g_qkv);
    cudaGetSymbolAddress((void**)&p_att, g_att);

    cudaFuncSetAttribute(flash_kernel,
                         cudaFuncAttributeMaxDynamicSharedMemorySize,
                         FA_SMEM_BYTES);

    // 1) qkv = x @ Wqkv   (tf32 tensor cores)
    {
        dim3 grid(NQKV / GBN, MROWS / GBM);  // 48 x 32
        tf32_gemm_kernel<<<grid, 256>>>(x, Wqkv, p_qkv, MROWS, NQKV, EMB);
    }
    // 2) RoPE + split/transpose to [B,H,S,D]
    {
        int total = BSZ * SEQ * NHEAD * (HDIM / 2);  // 2^22
        rope_split_kernel<<<total / 256, 256>>>(p_qkv, freqs);
    }
    // 3) causal flash attention (fp32)
    {
        dim3 grid(SEQ / 64, NHEAD, BSZ);     // 32 x 16 x 2
        flash_kernel<<<grid, 256, FA_SMEM_BYTES>>>();
    }
    // 4) out = att @ Wo   (tf32 tensor cores)
    {
        dim3 grid(EMB / GBN, MROWS / GBM);   // 16 x 32
        tf32_gemm_kernel<<<grid, 256>>>(p_att, Wo, out, MROWS, EMB, EMB);
    }
}

// round 5
// speedup vs baseline: 3.4442x; 1.8998x over previous
#include <cuda_runtime.h>
#include <cuda_bf16.h>
#include <cstdint>
#include <cstddef>

// ---------------------------------------------------------------------------
// Problem constants (fixed shapes: B=2, S=2048, E=2048, H=16, D=128)
// ---------------------------------------------------------------------------
#define BSZ   2
#define SEQ   2048
#define EMB   2048
#define NHEAD 16
#define HDIM  128
#define MROWS (BSZ * SEQ)      /* 4096 */
#define NQKV  (3 * EMB)        /* 6144 */

#define QK_SCALE 0.08838834764831845f  /* 128^-0.5 */

// ---------------------------------------------------------------------------
// Scratch (no cudaMalloc allowed -> __device__ globals)
// ---------------------------------------------------------------------------
__device__ float g_qkv[(size_t)MROWS * NQKV];                 // ~100 MB
__device__ float g_q[(size_t)BSZ * NHEAD * SEQ * HDIM];       // 33.6 MB
__device__ float g_k[(size_t)BSZ * NHEAD * SEQ * HDIM];
__device__ float g_v[(size_t)BSZ * NHEAD * SEQ * HDIM];
__device__ float g_att[(size_t)MROWS * EMB];                  // 33.6 MB

extern __shared__ unsigned char dyn_smem[];

__device__ __forceinline__ uint32_t smem_addr_u32(const void* p) {
    return (uint32_t)__cvta_generic_to_shared(p);
}
__device__ __forceinline__ uint32_t f2tf32(float f) {
    uint32_t r;
    asm("cvt.rna.tf32.f32 %0, %1;" : "=r"(r) : "f"(f));
    return r;
}
__device__ __forceinline__ void mma_tf32(float& d0, float& d1, float& d2, float& d3,
                                         uint32_t a0, uint32_t a1, uint32_t a2, uint32_t a3,
                                         uint32_t b0, uint32_t b1)
{
    asm volatile(
        "mma.sync.aligned.m16n8k8.row.col.f32.tf32.tf32.f32 "
        "{%0,%1,%2,%3}, {%4,%5,%6,%7}, {%8,%9}, {%0,%1,%2,%3};"
        : "+f"(d0), "+f"(d1), "+f"(d2), "+f"(d3)
        : "r"(a0), "r"(a1), "r"(a2), "r"(a3), "r"(b0), "r"(b1));
}
#define CP_ASYNC16(dst, src) \
    asm volatile("cp.async.ca.shared.global [%0], [%1], 16;\n" :: "r"(dst), "l"(src))
#define CP_COMMIT() asm volatile("cp.async.commit_group;\n")
#define CP_WAIT(n)  asm volatile("cp.async.wait_group %0;\n" :: "n"(n))

// ---------------------------------------------------------------------------
// TF32 tensor-core GEMM: C[M,N] = A[M,K] @ B[K,N].
// CTA 128x128x32, 256 threads, warp tile 64x32, double-buffered smem.
// ---------------------------------------------------------------------------
#define GBM 128
#define GBN 128
#define GBK 32
#define APITCH 36
#define BPITCH 136
#define GEMM_ABUF (GBM * APITCH)   /* 4608 u32 */
#define GEMM_BBUF (GBK * BPITCH)   /* 4352 u32 */
#define GEMM_BUF  (GEMM_ABUF + GEMM_BBUF)
#define GEMM_SMEM_BYTES (2 * GEMM_BUF * 4)   /* 71680 */

__global__ __launch_bounds__(256)
void tf32_gemm_kernel(const float* __restrict__ A, const float* __restrict__ B,
                      float* __restrict__ C, int M, int N, int K)
{
    uint32_t* sm = (uint32_t*)dyn_smem;

    const int tid  = threadIdx.x;
    const int lane = tid & 31;
    const int w    = tid >> 5;
    const int wm   = (w >> 2) * 64;
    const int wn   = (w & 3) * 32;
    const int g    = lane >> 2;
    const int t4   = lane & 3;

    const int m0 = blockIdx.y * GBM;
    const int n0 = blockIdx.x * GBN;

    const int a_row = tid >> 3;
    const int a_c4  = (tid & 7) << 2;
    const int b_row = tid >> 5;
    const int b_c4  = (tid & 31) << 2;

    const float* aP = A + (size_t)(m0 + a_row) * K + a_c4;
    const float* bP = B + (size_t)b_row * N + n0 + b_c4;

    float4 ra[4], rb[4];
    float d[4][4][4];
#pragma unroll
    for (int i = 0; i < 4; i++)
#pragma unroll
        for (int j = 0; j < 4; j++)
#pragma unroll
            for (int c = 0; c < 4; c++) d[i][j][c] = 0.f;

    const int nk = K / GBK;

#pragma unroll
    for (int it = 0; it < 4; ++it) {
        ra[it] = *(const float4*)(aP + (size_t)(it * 32) * K);
        rb[it] = *(const float4*)(bP + (size_t)(it * 8) * N);
    }

    for (int tkt = 0; tkt < nk; ++tkt) {
        uint32_t* As = sm + (tkt & 1) * GEMM_BUF;
        uint32_t* Bs = As + GEMM_ABUF;

        // store current regs -> this buffer (last read 2 iterations ago: safe)
#pragma unroll
        for (int it = 0; it < 4; ++it) {
            uint4 va = make_uint4(f2tf32(ra[it].x), f2tf32(ra[it].y),
                                  f2tf32(ra[it].z), f2tf32(ra[it].w));
            *(uint4*)&As[(a_row + it * 32) * APITCH + a_c4] = va;
            uint4 vb = make_uint4(f2tf32(rb[it].x), f2tf32(rb[it].y),
                                  f2tf32(rb[it].z), f2tf32(rb[it].w));
            *(uint4*)&Bs[(b_row + it * 8) * BPITCH + b_c4] = vb;
        }
        // prefetch next tile into registers (overlaps barrier + compute)
        if (tkt + 1 < nk) {
            const float* aN = aP + (size_t)(tkt + 1) * GBK;
            const float* bN = bP + (size_t)(tkt + 1) * GBK * N;
#pragma unroll
            for (int it = 0; it < 4; ++it) {
                ra[it] = *(const float4*)(aN + (size_t)(it * 32) * K);
                rb[it] = *(const float4*)(bN + (size_t)(it * 8) * N);
            }
        }
        __syncthreads();   // stores visible to all before compute

#pragma unroll
        for (int s = 0; s < 4; ++s) {
            const int kc = s * 8;
            uint32_t af[4][4], bf[4][2];
#pragma unroll
            for (int mf = 0; mf < 4; ++mf) {
                int r0 = wm + mf * 16 + g;
                af[mf][0] = As[r0 * APITCH + kc + t4];
                af[mf][1] = As[(r0 + 8) * APITCH + kc + t4];
                af[mf][2] = As[r0 * APITCH + kc + t4 + 4];
                af[mf][3] = As[(r0 + 8) * APITCH + kc + t4 + 4];
            }
#pragma unroll
            for (int nf = 0; nf < 4; ++nf) {
                int c0 = wn + nf * 8 + g;
                bf[nf][0] = Bs[(kc + t4) * BPITCH + c0];
                bf[nf][1] = Bs[(kc + t4 + 4) * BPITCH + c0];
            }
#pragma unroll
            for (int mf = 0; mf < 4; ++mf)
#pragma unroll
                for (int nf = 0; nf < 4; ++nf)
                    mma_tf32(d[mf][nf][0], d[mf][nf][1], d[mf][nf][2], d[mf][nf][3],
                             af[mf][0], af[mf][1], af[mf][2], af[mf][3],
                             bf[nf][0], bf[nf][1]);
        }
    }

#pragma unroll
    for (int mf = 0; mf < 4; ++mf) {
#pragma unroll
        for (int nf = 0; nf < 4; ++nf) {
            int row = m0 + wm + mf * 16 + g;
            int col = n0 + wn + nf * 8 + 2 * t4;
            float* cp0 = C + (size_t)row * N + col;
            float* cp1 = C + (size_t)(row + 8) * N + col;
            *(float2*)cp0 = make_float2(d[mf][nf][0], d[mf][nf][1]);
            *(float2*)cp1 = make_float2(d[mf][nf][2], d[mf][nf][3]);
        }
    }
}

// ---------------------------------------------------------------------------
// RoPE + reorder: qkv [B*S, 3E] -> Q/K/V [B, H, S, D], q pre-scaled by D^-0.5
// ---------------------------------------------------------------------------
__global__ void rope_split_kernel(const float* __restrict__ qkv,
                                  const float* __restrict__ freqs)
{
    int t = blockIdx.x * blockDim.x + threadIdx.x;
    int i = t & 63;
    int h = (t >> 6) & 15;
    int s = (t >> 10) & 2047;
    int b = t >> 21;

    size_t row = (size_t)(b * SEQ + s) * NQKV + h * HDIM;
    float2 q  = *(const float2*)&qkv[row + 2 * i];
    float2 k  = *(const float2*)&qkv[row + EMB + 2 * i];
    float2 v  = *(const float2*)&qkv[row + 2 * EMB + 2 * i];
    float2 cs = *(const float2*)&freqs[(size_t)s * HDIM + 2 * i];

    float qre = (q.x * cs.x - q.y * cs.y) * QK_SCALE;
    float qim = (q.y * cs.x + q.x * cs.y) * QK_SCALE;
    float kre = k.x * cs.x - k.y * cs.y;
    float kim = k.y * cs.x + k.x * cs.y;

    size_t o = ((size_t)(b * NHEAD + h) * SEQ + s) * HDIM + 2 * i;
    *(float2*)&g_q[o] = make_float2(qre, qim);
    *(float2*)&g_k[o] = make_float2(kre, kim);
    *(float2*)&g_v[o] = v;
}

// ---------------------------------------------------------------------------
// Flash attention (causal), tf32 tensor cores.
// BM=128 (8 warps x 16 rows), BN=64, D=128. Double-buffered cp.async K/V.
// K smem [n][d] pitch 132 (b-frag banks 4g+t distinct),
// V smem [kv][d] pitch 136 (b-frag banks 8t+g distinct).
// Q a-frags held in registers (tf32), reused across all KV tiles.
// P (c-frag) -> a-frag via in-quad shuffles; no P smem.
// ---------------------------------------------------------------------------
#define FKP 132
#define FVP 136
#define FBUF (64 * FKP + 64 * FVP)          /* 17152 floats */
#define FA_SMEM_BYTES (2 * FBUF * 4)        /* 137216 B */

__global__ __launch_bounds__(256, 1)
void flash_tc_kernel()
{
    float* fs = (float*)dyn_smem;

    const int tid  = threadIdx.x;
    const int lane = tid & 31;
    const int w    = tid >> 5;         // 0..7
    const int g    = lane >> 2;        // 0..7
    const int t4   = lane & 3;         // 0..3
    const int wm   = w * 16;           // warp row offset in 128-row block

    const int qb = blockIdx.x;         // 0..15 (128-row Q blocks)
    const int h  = blockIdx.y;
    const int b  = blockIdx.z;

    const size_t base = (size_t)(b * NHEAD + h) * SEQ * HDIM;
    const float* Qg = g_q + base + (size_t)qb * 128 * HDIM;
    const float* Kg = g_k + base;
    const float* Vg = g_v + base;

    // ---- stage Q (128x128) into fs (pitch FKP), then lift a-frags to regs ----
#pragma unroll
    for (int it = 0; it < 16; ++it) {
        int idx = tid + it * 256;
        int r  = idx >> 5;
        int c4 = (idx & 31) << 2;
        uint32_t dst = smem_addr_u32(&fs[r * FKP + c4]);
        CP_ASYNC16(dst, Qg + (size_t)r * HDIM + c4);
    }
    CP_COMMIT();
    CP_WAIT(0);
    __syncthreads();

    uint32_t qa[16][4];
#pragma unroll
    for (int ks = 0; ks < 16; ++ks) {
        int kc = ks * 8;
        qa[ks][0] = f2tf32(fs[(wm + g) * FKP + kc + t4]);
        qa[ks][1] = f2tf32(fs[(wm + g + 8) * FKP + kc + t4]);
        qa[ks][2] = f2tf32(fs[(wm + g) * FKP + kc + t4 + 4]);
        qa[ks][3] = f2tf32(fs[(wm + g + 8) * FKP + kc + t4 + 4]);
    }
    __syncthreads();   // all Q reads done before cp.async overwrites buffer 0

    float m0 = -1e30f, m1 = -1e30f, l0 = 0.f, l1 = 0.f;
    float accO[16][4];
#pragma unroll
    for (int i = 0; i < 16; i++)
#pragma unroll
        for (int c = 0; c < 4; c++) accO[i][c] = 0.f;

    const int row0 = qb * 128 + wm + g;     // global q row (this lane, frag row 0)
    const int row1 = row0 + 8;
    const int nt   = 2 * qb + 2;            // 64-col KV tiles

    // K/V tile loader (cp.async)
    const int kv_r  = tid >> 5;             // +8*it
    const int kv_c4 = (tid & 31) << 2;

#define FA_ISSUE(T, BUF)                                                      \
    do {                                                                      \
        float* kb_ = fs + (BUF) * FBUF;                                       \
        float* vb_ = kb_ + 64 * FKP;                                          \
        _Pragma("unroll")                                                     \
        for (int it_ = 0; it_ < 8; ++it_) {                                   \
            int r_ = kv_r + it_ * 8;                                          \
            size_t go_ = (size_t)((T) * 64 + r_) * HDIM + kv_c4;              \
            CP_ASYNC16(smem_addr_u32(&kb_[r_ * FKP + kv_c4]), Kg + go_);      \
            CP_ASYNC16(smem_addr_u32(&vb_[r_ * FVP + kv_c4]), Vg + go_);      \
        }                                                                     \
        CP_COMMIT();                                                          \
    } while (0)

    FA_ISSUE(0, 0);

    for (int t = 0; t < nt; ++t) {
        if (t + 1 < nt) { FA_ISSUE(t + 1, (t + 1) & 1); CP_WAIT(1); }
        else            { CP_WAIT(0); }
        __syncthreads();

        const float* Ks = fs + (t & 1) * FBUF;
        const float* Vs = Ks + 64 * FKP;
        const int colbase = t * 64;

        // whole 16x64 block above diagonal? (uniform per warp) -> skip compute
        const bool dead = (colbase > qb * 128 + wm + 15);
        if (!dead) {
            // ---- S = Q . K^T ----
            float sc[8][4];
#pragma unroll
            for (int nf = 0; nf < 8; ++nf)
#pragma unroll
                for (int c = 0; c < 4; c++) sc[nf][c] = 0.f;

#pragma unroll
            for (int ks = 0; ks < 16; ++ks) {
                int kc = ks * 8;
#pragma unroll
                for (int nf = 0; nf < 8; ++nf) {
                    int c0 = nf * 8 + g;
                    uint32_t b0 = f2tf32(Ks[c0 * FKP + kc + t4]);
                    uint32_t b1 = f2tf32(Ks[c0 * FKP + kc + t4 + 4]);
                    mma_tf32(sc[nf][0], sc[nf][1], sc[nf][2], sc[nf][3],
                             qa[ks][0], qa[ks][1], qa[ks][2], qa[ks][3], b0, b1);
                }
            }

            // ---- causal mask ----
            if (colbase + 63 > row0) {
#pragma unroll
                for (int nf = 0; nf < 8; ++nf) {
                    int c = colbase + nf * 8 + 2 * t4;
                    if (c     > row0) sc[nf][0] = -1e30f;
                    if (c + 1 > row0) sc[nf][1] = -1e30f;
                    if (c     > row1) sc[nf][2] = -1e30f;
                    if (c + 1 > row1) sc[nf][3] = -1e30f;
                }
            }

            // ---- online softmax (rows g, g+8) ----
            float mx0 = -1e30f, mx1 = -1e30f;
#pragma unroll
            for (int nf = 0; nf < 8; ++nf) {
                mx0 = fmaxf(mx0, fmaxf(sc[nf][0], sc[nf][1]));
                mx1 = fmaxf(mx1, fmaxf(sc[nf][2], sc[nf][3]));
            }
            mx0 = fmaxf(mx0, __shfl_xor_sync(0xffffffffu, mx0, 1));
            mx0 = fmaxf(mx0, __shfl_xor_sync(0xffffffffu, mx0, 2));
            mx1 = fmaxf(mx1, __shfl_xor_sync(0xffffffffu, mx1, 1));
            mx1 = fmaxf(mx1, __shfl_xor_sync(0xffffffffu, mx1, 2));

            float nm0 = fmaxf(m0, mx0), nm1 = fmaxf(m1, mx1);
            float s0 = __expf(m0 - nm0), s1 = __expf(m1 - nm1);
            float rs0 = 0.f, rs1 = 0.f;
#pragma unroll
            for (int nf = 0; nf < 8; ++nf) {
                sc[nf][0] = __expf(sc[nf][0] - nm0);
                sc[nf][1] = __expf(sc[nf][1] - nm0);
                sc[nf][2] = __expf(sc[nf][2] - nm1);
                sc[nf][3] = __expf(sc[nf][3] - nm1);
                rs0 += sc[nf][0] + sc[nf][1];
                rs1 += sc[nf][2] + sc[nf][3];
            }
            rs0 += __shfl_xor_sync(0xffffffffu, rs0, 1);
            rs0 += __shfl_xor_sync(0xffffffffu, rs0, 2);
            rs1 += __shfl_xor_sync(0xffffffffu, rs1, 1);
            rs1 += __shfl_xor_sync(0xffffffffu, rs1, 2);
            l0 = l0 * s0 + rs0;  m0 = nm0;
            l1 = l1 * s1 + rs1;  m1 = nm1;

#pragma unroll
            for (int nf = 0; nf < 16; ++nf) {
                accO[nf][0] *= s0; accO[nf][1] *= s0;
                accO[nf][2] *= s1; accO[nf][3] *= s1;
            }

            // ---- O += P . V  (P c-frag -> a-frag via quad shuffles) ----
            const int srcA = (lane & ~3) | (t4 >> 1);
            const int srcB = srcA + 2;
            const int e = t4 & 1;
#pragma unroll
            for (int ks = 0; ks < 8; ++ks) {
                float x0a = __shfl_sync(0xffffffffu, sc[ks][0], srcA);
                float x1a = __shfl_sync(0xffffffffu, sc[ks][1], srcA);
                float x2a = __shfl_sync(0xffffffffu, sc[ks][2], srcA);
                float x3a = __shfl_sync(0xffffffffu, sc[ks][3], srcA);
                float x0b = __shfl_sync(0xffffffffu, sc[ks][0], srcB);
                float x1b = __shfl_sync(0xffffffffu, sc[ks][1], srcB);
                float x2b = __shfl_sync(0xffffffffu, sc[ks][2], srcB);
                float x3b = __shfl_sync(0xffffffffu, sc[ks][3], srcB);
                uint32_t a0 = f2tf32(e ? x1a : x0a);   // (row g,   col t4)
                uint32_t a1 = f2tf32(e ? x3a : x2a);   // (row g+8, col t4)
                uint32_t a2 = f2tf32(e ? x1b : x0b);   // (row g,   col t4+4)
                uint32_t a3 = f2tf32(e ? x3b : x2b);   // (row g+8, col t4+4)
                const int vr0 = (ks * 8 + t4) * FVP;
                const int vr1 = (ks * 8 + t4 + 4) * FVP;
#pragma unroll
                for (int nf = 0; nf < 16; ++nf) {
                    uint32_t b0 = f2tf32(Vs[vr0 + nf * 8 + g]);
                    uint32_t b1 = f2tf32(Vs[vr1 + nf * 8 + g]);
                    mma_tf32(accO[nf][0], accO[nf][1], accO[nf][2], accO[nf][3],
                             a0, a1, a2, a3, b0, b1);
                }
            }
        }
        __syncthreads();   // compute done before next issue overwrites other buf
    }

    // ---- epilogue: normalize + write [B, S, H*D] ----
    float i0 = 1.f / l0, i1 = 1.f / l1;
    float* o0 = g_att + ((size_t)b * SEQ + row0) * EMB + h * HDIM;
    float* o1 = g_att + ((size_t)b * SEQ + row1) * EMB + h * HDIM;
#pragma unroll
    for (int nf = 0; nf < 16; ++nf) {
        int col = nf * 8 + 2 * t4;
        *(float2*)&o0[col] = make_float2(accO[nf][0] * i0, accO[nf][1] * i0);
        *(float2*)&o1[col] = make_float2(accO[nf][2] * i1, accO[nf][3] * i1);
    }
}

// ---------------------------------------------------------------------------
// Launcher
// ---------------------------------------------------------------------------
extern "C" void kernel_launch(void* const* d_in, const int* in_sizes, int n_in,
                              void* d_out, int out_size)
{
    const float* x     = (const float*)d_in[0];
    const float* Wqkv  = (const float*)d_in[1];
    const float* Wo    = (const float*)d_in[2];
    const float* freqs = (const float*)d_in[3];
    float* out = (float*)d_out;

    float *p_qkv = nullptr, *p_att = nullptr;
    cudaGetSymbolAddress((void**)&p_qkv, g_qkv);
    cudaGetSymbolAddress((void**)&p_att, g_att);

    cudaFuncSetAttribute(tf32_gemm_kernel,
                         cudaFuncAttributeMaxDynamicSharedMemorySize,
                         GEMM_SMEM_BYTES);
    cudaFuncSetAttribute(flash_tc_kernel,
                         cudaFuncAttributeMaxDynamicSharedMemorySize,
                         FA_SMEM_BYTES);

    // 1) qkv = x @ Wqkv   (tf32 tensor cores)
    {
        dim3 grid(NQKV / GBN, MROWS / GBM);  // 48 x 32
        tf32_gemm_kernel<<<grid, 256, GEMM_SMEM_BYTES>>>(x, Wqkv, p_qkv,
                                                         MROWS, NQKV, EMB);
    }
    // 2) RoPE + split/transpose to [B,H,S,D]
    {
        int total = BSZ * SEQ * NHEAD * (HDIM / 2);
        rope_split_kernel<<<total / 256, 256>>>(p_qkv, freqs);
    }
    // 3) causal flash attention (tf32 tensor cores)
    {
        dim3 grid(SEQ / 128, NHEAD, BSZ);    // 16 x 16 x 2
        flash_tc_kernel<<<grid, 256, FA_SMEM_BYTES>>>();
    }
    // 4) out = att @ Wo   (tf32 tensor cores)
    {
        dim3 grid(EMB / GBN, MROWS / GBM);   // 16 x 32
        tf32_gemm_kernel<<<grid, 256, GEMM_SMEM_BYTES>>>(p_att, Wo, out,
                                                         MROWS, EMB, EMB);
    }
}